// round 11
// baseline (speedup 1.0000x reference)
#include <cuda_runtime.h>
#include <math.h>

#define N 512
#define M 512
#define D 512
#define HG 256
#define R 256
#define H 128

// ---------------- device scratch ----------------
__device__ float d_rep[3][N][R];
__device__ float d_norm2[3][N];
__device__ float d_Wxd[R * H];
__device__ float d_Wyd[R * H];
__device__ float d_A[N * H];        // pre-scaled by 1/sqrt(2)
__device__ float d_Bt[2][H * M];    // pre-scaled by 1/sqrt(2)
__device__ float d_G[2][2][N * M];  // gram split-K partials
__device__ float d_W[2][N * M];
__device__ float d_Upart[8][N][R];
__device__ float d_Qb[2][M];
__device__ float d_Qw;

#define INV_SQRT2 0.7071067811865476f

__device__ __forceinline__ float gelu_exact(float x) {
    return 0.5f * x * (1.0f + erff(x * INV_SQRT2));
}

// ================= K1: fused g-MLP, Wxd/Wyd combine, Qw =================
__global__ void __launch_bounds__(256) k1_gmlp(
    const float* __restrict__ fx, const float* __restrict__ fp, const float* __restrict__ fn,
    const float* __restrict__ w1, const float* __restrict__ b1,
    const float* __restrict__ w2, const float* __restrict__ b2,
    const float* __restrict__ s_w1, const float* __restrict__ s_w2)
{
    int bid = blockIdx.x;
    int tid = threadIdx.x;
    __shared__ float qr[4];

    if (bid == 224) {
        float v = 0.f;
        if (tid < 128) v = 0.5f * s_w2[tid] * s_w1[3 * R * H + tid];
#pragma unroll
        for (int o = 16; o; o >>= 1) v += __shfl_xor_sync(0xFFFFFFFFu, v, o);
        if (tid < 128 && (tid & 31) == 0) qr[tid >> 5] = v;
        __syncthreads();
        if (tid == 0) d_Qw = qr[0] + qr[1] + qr[2] + qr[3];
        return;
    }
    if (bid >= 192) {
        int i0 = (bid - 192) * 1024 + tid;
#pragma unroll
        for (int t = 0; t < 4; t++) {
            int i = i0 + t * 256;
            float wd = s_w1[2 * R * H + i];
            d_Wxd[i] = s_w1[i] - wd;
            d_Wyd[i] = s_w1[R * H + i] + wd;
        }
        return;
    }

    int mi = bid / 64;
    int r0 = (bid % 64) * 8;
    const float* X = (mi == 0) ? fx : (mi == 1 ? fp : fn);

    __shared__ float xs[8][D];
    __shared__ float hs[8][HG];
    __shared__ float wsum[8][8];

    for (int i = tid; i < 8 * D; i += 256)
        xs[i / D][i % D] = X[(r0 + i / D) * D + (i % D)];
    __syncthreads();

    int j = tid;
    float acc[8];
#pragma unroll
    for (int r = 0; r < 8; r++) acc[r] = 0.f;
    for (int k = 0; k < D; k += 4) {
        float w0  = w1[(k + 0) * HG + j];
        float w1v = w1[(k + 1) * HG + j];
        float w2v = w1[(k + 2) * HG + j];
        float w3  = w1[(k + 3) * HG + j];
#pragma unroll
        for (int r = 0; r < 8; r++) {
            float4 xv = *(const float4*)&xs[r][k];
            acc[r] = fmaf(xv.x, w0, acc[r]);
            acc[r] = fmaf(xv.y, w1v, acc[r]);
            acc[r] = fmaf(xv.z, w2v, acc[r]);
            acc[r] = fmaf(xv.w, w3, acc[r]);
        }
    }
    float bb = b1[j];
#pragma unroll
    for (int r = 0; r < 8; r++) hs[r][j] = gelu_exact(acc[r] + bb);
    __syncthreads();

    float a2[8];
#pragma unroll
    for (int r = 0; r < 8; r++) a2[r] = 0.f;
    for (int k = 0; k < HG; k += 4) {
        float w0  = w2[(k + 0) * R + j];
        float w1v = w2[(k + 1) * R + j];
        float w2v = w2[(k + 2) * R + j];
        float w3  = w2[(k + 3) * R + j];
#pragma unroll
        for (int r = 0; r < 8; r++) {
            float4 hv = *(const float4*)&hs[r][k];
            a2[r] = fmaf(hv.x, w0, a2[r]);
            a2[r] = fmaf(hv.y, w1v, a2[r]);
            a2[r] = fmaf(hv.z, w2v, a2[r]);
            a2[r] = fmaf(hv.w, w3, a2[r]);
        }
    }
    float b2v = b2[j];
    int w = tid >> 5, lane = tid & 31;
#pragma unroll
    for (int r = 0; r < 8; r++) {
        float v = a2[r] + b2v;
        d_rep[mi][r0 + r][j] = v;
        float s = v * v;
#pragma unroll
        for (int o = 16; o; o >>= 1) s += __shfl_xor_sync(0xFFFFFFFFu, s, o);
        if (lane == 0) wsum[w][r] = s;
    }
    __syncthreads();
    if (tid < 8) {
        float s = 0.f;
#pragma unroll
        for (int ww = 0; ww < 8; ww++) s += wsum[ww][tid];
        d_norm2[mi][r0 + tid] = s;
    }
}

// ================= K2: Gram (split-K) + A/Bt (+Qb) =================
__global__ void __launch_bounds__(256) k2_gram_ab(
    const float* __restrict__ s_b1, const float* __restrict__ s_w2)
{
    __shared__ float smbuf[2 * 32 * 68];
    __shared__ float qred[4][8];
    int bid = blockIdx.x;
    int tid = threadIdx.x;

    if (bid < 256) {
        int set = bid >> 7;
        int kh = (bid >> 6) & 1;
        int tt = bid & 63;
        int bn = (tt >> 3) * 64;
        int bm = (tt & 7) * 64;
        float (*xs)[68]  = (float(*)[68])smbuf;
        float (*ysm)[68] = (float(*)[68])(smbuf + 32 * 68);
        int ty = tid >> 4, tx = tid & 15;

        float acc[4][4];
#pragma unroll
        for (int i = 0; i < 4; i++)
#pragma unroll
            for (int jj = 0; jj < 4; jj++) acc[i][jj] = 0.f;

        for (int kc = kh * 4; kc < kh * 4 + 4; kc++) {
            __syncthreads();
#pragma unroll
            for (int p = 0; p < 8; p++) {
                int i = tid + p * 256;
                int n = i >> 5, k = i & 31;
                xs[k][n]  = d_rep[0][bn + n][kc * 32 + k];
                ysm[k][n] = d_rep[set + 1][bm + n][kc * 32 + k];
            }
            __syncthreads();
#pragma unroll
            for (int k = 0; k < 32; k++) {
                float4 xv = *(const float4*)&xs[k][ty * 4];
                float4 yv = *(const float4*)&ysm[k][tx * 4];
                float xa[4] = {xv.x, xv.y, xv.z, xv.w};
                float ya[4] = {yv.x, yv.y, yv.z, yv.w};
#pragma unroll
                for (int i = 0; i < 4; i++)
#pragma unroll
                    for (int jj = 0; jj < 4; jj++) acc[i][jj] += xa[i] * ya[jj];
            }
        }
#pragma unroll
        for (int i = 0; i < 4; i++) {
            float4 o = make_float4(acc[i][0], acc[i][1], acc[i][2], acc[i][3]);
            *(float4*)&d_G[set][kh][(bn + ty * 4 + i) * M + bm + tx * 4] = o;
        }
    } else {
        int ab = bid - 256;
        int mi = ab / 64;
        int r0 = (ab % 64) * 8;
        float (*ys)[R] = (float(*)[R])smbuf;
        float (*ps)[H] = (float(*)[H])(smbuf + 8 * R);

        for (int i = tid; i < 8 * R; i += 256)
            ys[i / R][i % R] = d_rep[mi][r0 + i / R][i % R];
        __syncthreads();

        int h = tid & 127;
        int half = tid >> 7;
        const float* Wc = (mi == 0) ? d_Wxd : d_Wyd;
        float acc[8];
#pragma unroll
        for (int r = 0; r < 8; r++) acc[r] = 0.f;
        int kbeg = half * 128;
        for (int k = kbeg; k < kbeg + 128; k += 4) {
            float w0  = Wc[(k + 0) * H + h];
            float w1v = Wc[(k + 1) * H + h];
            float w2v = Wc[(k + 2) * H + h];
            float w3  = Wc[(k + 3) * H + h];
#pragma unroll
            for (int r = 0; r < 8; r++) {
                float4 yv = *(const float4*)&ys[r][k];
                acc[r] = fmaf(yv.x, w0, acc[r]);
                acc[r] = fmaf(yv.y, w1v, acc[r]);
                acc[r] = fmaf(yv.z, w2v, acc[r]);
                acc[r] = fmaf(yv.w, w3, acc[r]);
            }
        }
        if (half == 1) {
#pragma unroll
            for (int r = 0; r < 8; r++) ps[r][h] = acc[r];
        }
        __syncthreads();
        if (half == 0) {
            if (mi == 0) {
                float bb = s_b1[h];
#pragma unroll
                for (int r = 0; r < 8; r++)
                    d_A[(r0 + r) * H + h] = (acc[r] + ps[r][h] + bb) * INV_SQRT2;
            } else {
                float s2h = 0.70710678f * s_w2[h];
                int w = tid >> 5, lane = tid & 31;
#pragma unroll
                for (int r = 0; r < 8; r++) {
                    float btv = (acc[r] + ps[r][h]) * INV_SQRT2;
                    d_Bt[mi - 1][h * M + (r0 + r)] = btv;
                    float pr = s2h * btv;
#pragma unroll
                    for (int o = 16; o; o >>= 1) pr += __shfl_xor_sync(0xFFFFFFFFu, pr, o);
                    if (lane == 0) qred[w][r] = pr;
                }
            }
        }
        __syncthreads();
        if (mi > 0 && tid < 8)
            d_Qb[mi - 1][r0 + tid] = qred[0][tid] + qred[1][tid] + qred[2][tid] + qred[3][tid];
    }
}

// ================= K3: score + softmax (2 n-rows/block, lean erf loop) =================
// grid = 2 sets x 256 = 512 blocks; thread owns m = 2*tid, 2*tid+1 for both rows
__global__ void __launch_bounds__(256) k3_score(
    const float* __restrict__ s_w1, const float* __restrict__ s_w2)
{
    int set = blockIdx.x >> 8;
    int n0 = (blockIdx.x & 255) * 2;
    __shared__ float As0[H];
    __shared__ float As1[H];
    __shared__ float2 ws[H];   // (wnh, s2h)
    __shared__ float red[32];

    int tid = threadIdx.x;
    if (tid < H) {
        As0[tid] = d_A[n0 * H + tid];
        As1[tid] = d_A[(n0 + 1) * H + tid];
        float wn = s_w1[3 * R * H + tid] * INV_SQRT2;
        float s2 = s_w2[tid] * 0.70710678f;
        ws[tid] = make_float2(wn, s2);
    }
    __syncthreads();

    float nx0 = d_norm2[0][n0];
    float nx1 = d_norm2[0][n0 + 1];
    float2 ny = *(const float2*)&d_norm2[set + 1][2 * tid];
    float2 ga0 = *(const float2*)&d_G[set][0][n0 * M + 2 * tid];
    float2 gb0 = *(const float2*)&d_G[set][1][n0 * M + 2 * tid];
    float2 ga1 = *(const float2*)&d_G[set][0][(n0 + 1) * M + 2 * tid];
    float2 gb1 = *(const float2*)&d_G[set][1][(n0 + 1) * M + 2 * tid];
    float t00 = sqrtf(fmaxf(nx0 + ny.x - 2.f * (ga0.x + gb0.x), 0.f));
    float t01 = sqrtf(fmaxf(nx0 + ny.y - 2.f * (ga0.y + gb0.y), 0.f));
    float t10 = sqrtf(fmaxf(nx1 + ny.x - 2.f * (ga1.x + gb1.x), 0.f));
    float t11 = sqrtf(fmaxf(nx1 + ny.y - 2.f * (ga1.y + gb1.y), 0.f));
    float2 qb = *(const float2*)&d_Qb[set][2 * tid];
    float qw = d_Qw;

    float acc00 = 0.f, acc01 = 0.f, acc10 = 0.f, acc11 = 0.f;
    const float2* Bt2 = (const float2*)&d_Bt[set][0];

#define ERF_ACC(T, AB, ACC, S2) do { \
        float p_ = fmaf((T), wn_, (AB)); \
        float ap_ = fabsf(p_); \
        float dd_ = fmaf(0.47047f, ap_, 1.f); \
        float rc_; asm("rcp.approx.f32 %0,%1;" : "=f"(rc_) : "f"(dd_)); \
        float hh_ = fmaf(-0.7478556f, rc_, 0.0958798f); \
        hh_ = fmaf(hh_, rc_, -0.3480242f); \
        float pln_ = hh_ * rc_; \
        float ex_ = __expf(-p_ * p_); \
        float qs_ = (S2) * ap_; \
        float u_ = fmaf(pln_, ex_, 1.0f); \
        ACC = fmaf(qs_, u_, ACC); \
    } while (0)

#pragma unroll 2
    for (int k = 0; k < H; k++) {
        float2 bv = Bt2[k * 256 + tid];
        float a0 = As0[k];
        float a1 = As1[k];
        float2 wsp = ws[k];
        float wn_ = wsp.x, s2_ = wsp.y;
        ERF_ACC(t00, a0 + bv.x, acc00, s2_);
        ERF_ACC(t01, a0 + bv.y, acc01, s2_);
        ERF_ACC(t10, a1 + bv.x, acc10, s2_);
        ERF_ACC(t11, a1 + bv.y, acc11, s2_);
    }
#undef ERF_ACC

    float l00 = fmaf(t00, qw, qb.x) + acc00;
    float l01 = fmaf(t01, qw, qb.y) + acc01;
    float l10 = fmaf(t10, qw, qb.x) + acc10;
    float l11 = fmaf(t11, qw, qb.y) + acc11;

    int w = tid >> 5, lane = tid & 31;
    float mx0 = fmaxf(l00, l01);
    float mx1 = fmaxf(l10, l11);
#pragma unroll
    for (int o = 16; o; o >>= 1) {
        mx0 = fmaxf(mx0, __shfl_xor_sync(0xFFFFFFFFu, mx0, o));
        mx1 = fmaxf(mx1, __shfl_xor_sync(0xFFFFFFFFu, mx1, o));
    }
    if (lane == 0) { red[w] = mx0; red[8 + w] = mx1; }
    __syncthreads();
    mx0 = red[0]; mx1 = red[8];
#pragma unroll
    for (int i = 1; i < 8; i++) {
        mx0 = fmaxf(mx0, red[i]);
        mx1 = fmaxf(mx1, red[8 + i]);
    }
    float e00 = __expf(l00 - mx0), e01 = __expf(l01 - mx0);
    float e10 = __expf(l10 - mx1), e11 = __expf(l11 - mx1);
    float s0 = e00 + e01, s1 = e10 + e11;
#pragma unroll
    for (int o = 16; o; o >>= 1) {
        s0 += __shfl_xor_sync(0xFFFFFFFFu, s0, o);
        s1 += __shfl_xor_sync(0xFFFFFFFFu, s1, o);
    }
    if (lane == 0) { red[16 + w] = s0; red[24 + w] = s1; }
    __syncthreads();
    s0 = red[16]; s1 = red[24];
#pragma unroll
    for (int i = 1; i < 8; i++) { s0 += red[16 + i]; s1 += red[24 + i]; }
    float inv0 = 1.f / s0, inv1 = 1.f / s1;
    *(float2*)&d_W[set][n0 * M + 2 * tid] = make_float2(e00 * inv0, e01 * inv0);
    *(float2*)&d_W[set][(n0 + 1) * M + 2 * tid] = make_float2(e10 * inv1, e11 * inv1);
}

// ================= K4a: U partials, 64x64 tiles, 4x4 micro, 8-way M split =================
// grid = 32 tiles (8n x 4r) x 8 ms = 256 blocks, 256 threads
__global__ void __launch_bounds__(256) k4a_u()
{
    __shared__ float w_s[2][2][16][68];   // [buf][set][m][n]  (68*4=272B rows, 16B-divisible)
    __shared__ float yp_s[2][16][64];
    __shared__ float yn_s[2][16][64];

    int bid = blockIdx.x;
    int ms = bid & 7;
    int tile = bid >> 3;
    int bn = (tile >> 2) * 64;
    int br = (tile & 3) * 64;
    int tid = threadIdx.x;
    int ty = tid >> 4;
    int tx = tid & 15;

    // load roles
    int wset = tid >> 7;              // 0,1
    int widx = tid & 127;
    int wn_l = widx >> 1;             // 0..63
    int wm_l = (widx & 1) * 8;        // 0 or 8
    int ykk = tid >> 4;               // 0..15
    int yc = (tid & 15) * 4;

    float acc[4][4];
#pragma unroll
    for (int i = 0; i < 4; i++)
#pragma unroll
        for (int j = 0; j < 4; j++) acc[i][j] = 0.f;

    int mbase = ms * 64;
    float4 wv0, wv1, ypv, ynv;
    {
        const float* wrow = &d_W[wset][(bn + wn_l) * M + mbase + wm_l];
        wv0 = *(const float4*)&wrow[0];
        wv1 = *(const float4*)&wrow[4];
        ypv = *(const float4*)&d_rep[1][mbase + ykk][br + yc];
        ynv = *(const float4*)&d_rep[2][mbase + ykk][br + yc];
    }
    {
        float wa[8] = {wv0.x, wv0.y, wv0.z, wv0.w, wv1.x, wv1.y, wv1.z, wv1.w};
#pragma unroll
        for (int q = 0; q < 8; q++) w_s[0][wset][wm_l + q][wn_l] = wa[q];
        *(float4*)&yp_s[0][ykk][yc] = ypv;
        *(float4*)&yn_s[0][ykk][yc] = ynv;
    }
    __syncthreads();

    int buf = 0;
    for (int mc = 0; mc < 4; mc++) {
        if (mc < 3) {
            int mrow = mbase + (mc + 1) * 16;
            const float* wrow = &d_W[wset][(bn + wn_l) * M + mrow + wm_l];
            wv0 = *(const float4*)&wrow[0];
            wv1 = *(const float4*)&wrow[4];
            ypv = *(const float4*)&d_rep[1][mrow + ykk][br + yc];
            ynv = *(const float4*)&d_rep[2][mrow + ykk][br + yc];
        }
#pragma unroll
        for (int kk = 0; kk < 16; kk++) {
            float4 wp = *(const float4*)&w_s[buf][0][kk][ty * 4];
            float4 wq = *(const float4*)&w_s[buf][1][kk][ty * 4];
            float4 yp = *(const float4*)&yp_s[buf][kk][tx * 4];
            float4 yn = *(const float4*)&yn_s[buf][kk][tx * 4];
            float wpa[4] = {wp.x, wp.y, wp.z, wp.w};
            float wqa[4] = {wq.x, wq.y, wq.z, wq.w};
            float ypa[4] = {yp.x, yp.y, yp.z, yp.w};
            float yna[4] = {yn.x, yn.y, yn.z, yn.w};
#pragma unroll
            for (int i = 0; i < 4; i++)
#pragma unroll
                for (int j = 0; j < 4; j++) {
                    acc[i][j] = fmaf(wpa[i], ypa[j], acc[i][j]);
                    acc[i][j] = fmaf(-wqa[i], yna[j], acc[i][j]);
                }
        }
        if (mc < 3) {
            __syncthreads();
            int nb = buf ^ 1;
            float wa[8] = {wv0.x, wv0.y, wv0.z, wv0.w, wv1.x, wv1.y, wv1.z, wv1.w};
#pragma unroll
            for (int q = 0; q < 8; q++) w_s[nb][wset][wm_l + q][wn_l] = wa[q];
            *(float4*)&yp_s[nb][ykk][yc] = ypv;
            *(float4*)&yn_s[nb][ykk][yc] = ynv;
            __syncthreads();
            buf = nb;
        }
    }
#pragma unroll
    for (int i = 0; i < 4; i++) {
        float4 o = make_float4(acc[i][0], acc[i][1], acc[i][2], acc[i][3]);
        *(float4*)&d_Upart[ms][bn + ty * 4 + i][br + tx * 4] = o;
    }
}

// ================= K4b: out = (sum of 8 U partials) @ out_w =================
__global__ void __launch_bounds__(256) k4b_out(const float* __restrict__ out_w,
                                               float* __restrict__ out)
{
    __shared__ float us[16][36];
    __shared__ float ws[16][64];

    int bid = blockIdx.x;
    int bn = (bid >> 3) * 32;
    int bd = (bid & 7) * 64;
    int tid = threadIdx.x;
    int ty = tid >> 4, tx = tid & 15;

    float acc[2][4];
#pragma unroll
    for (int i = 0; i < 2; i++)
#pragma unroll
        for (int j = 0; j < 4; j++) acc[i][j] = 0.f;

    int un = tid >> 2;
    int uk = (tid & 3) * 4;
    int t2 = tid - 128;
    int wkk = t2 >> 3;
    int wc = (t2 & 7) * 8;

    for (int kc = 0; kc < R / 16; kc++) {
        float4 uv; float4 wv0, wv1;
        if (tid < 128) {
            float4 p[8];
#pragma unroll
            for (int q = 0; q < 8; q++)
                p[q] = *(const float4*)&d_Upart[q][bn + un][kc * 16 + uk];
            uv = p[0];
#pragma unroll
            for (int q = 1; q < 8; q++) {
                uv.x += p[q].x; uv.y += p[q].y; uv.z += p[q].z; uv.w += p[q].w;
            }
        } else {
            wv0 = *(const float4*)&out_w[(kc * 16 + wkk) * D + bd + wc];
            wv1 = *(const float4*)&out_w[(kc * 16 + wkk) * D + bd + wc + 4];
        }
        __syncthreads();
        if (tid < 128) {
            us[uk + 0][un] = uv.x;
            us[uk + 1][un] = uv.y;
            us[uk + 2][un] = uv.z;
            us[uk + 3][un] = uv.w;
        } else {
            *(float4*)&ws[wkk][wc] = wv0;
            *(float4*)&ws[wkk][wc + 4] = wv1;
        }
        __syncthreads();
#pragma unroll
        for (int kk = 0; kk < 16; kk++) {
            float2 u01 = *(const float2*)&us[kk][ty * 2];
            float4 w4 = *(const float4*)&ws[kk][tx * 4];
            float wa[4] = {w4.x, w4.y, w4.z, w4.w};
#pragma unroll
            for (int j = 0; j < 4; j++) {
                acc[0][j] += u01.x * wa[j];
                acc[1][j] += u01.y * wa[j];
            }
        }
    }
#pragma unroll
    for (int i = 0; i < 2; i++) {
        float4 o = make_float4(acc[i][0], acc[i][1], acc[i][2], acc[i][3]);
        *(float4*)&out[(bn + ty * 2 + i) * D + bd + tx * 4] = o;
    }
}

// ---------------- launch ----------------
extern "C" void kernel_launch(void* const* d_in, const int* in_sizes, int n_in,
                              void* d_out, int out_size)
{
    const float* feat_x  = (const float*)d_in[0];
    const float* feat_pos= (const float*)d_in[1];
    const float* feat_neg= (const float*)d_in[2];
    const float* g_w1    = (const float*)d_in[3];
    const float* g_b1    = (const float*)d_in[4];
    const float* g_w2    = (const float*)d_in[5];
    const float* g_b2    = (const float*)d_in[6];
    const float* out_w   = (const float*)d_in[7];
    const float* s_w1    = (const float*)d_in[8];
    const float* s_b1    = (const float*)d_in[9];
    const float* s_w2    = (const float*)d_in[10];
    float* out = (float*)d_out;
    (void)in_sizes; (void)n_in; (void)out_size;

    k1_gmlp<<<225, 256>>>(feat_x, feat_pos, feat_neg, g_w1, g_b1, g_w2, g_b2, s_w1, s_w2);
    k2_gram_ab<<<448, 256>>>(s_b1, s_w2);
    k3_score<<<512, 256>>>(s_w1, s_w2);
    k4a_u<<<256, 256>>>();
    k4b_out<<<128, 256>>>(out_w, out);
}

// round 12
// speedup vs baseline: 1.0865x; 1.0865x over previous
#include <cuda_runtime.h>
#include <math.h>

#define N 512
#define M 512
#define D 512
#define HG 256
#define R 256
#define H 128

// ---------------- device scratch ----------------
__device__ float d_rep[3][N][R];
__device__ float d_norm2[3][N];
__device__ float d_Wxd[R * H];
__device__ float d_Wyd[R * H];
__device__ float d_A[N * H];        // pre-scaled by 1/sqrt(2)
__device__ float d_Bt[2][H * M];    // pre-scaled by 1/sqrt(2)
__device__ float d_G[2][2][N * M];  // gram split-K partials
__device__ float d_W[2][N * M];
__device__ float d_Upart[8][N][R];
__device__ float d_Qb[2][M];
__device__ float d_Qw;

#define INV_SQRT2 0.7071067811865476f

__device__ __forceinline__ float gelu_exact(float x) {
    return 0.5f * x * (1.0f + erff(x * INV_SQRT2));
}

// ================= K1: fused g-MLP, Wxd/Wyd combine, Qw =================
__global__ void __launch_bounds__(256) k1_gmlp(
    const float* __restrict__ fx, const float* __restrict__ fp, const float* __restrict__ fn,
    const float* __restrict__ w1, const float* __restrict__ b1,
    const float* __restrict__ w2, const float* __restrict__ b2,
    const float* __restrict__ s_w1, const float* __restrict__ s_w2)
{
    int bid = blockIdx.x;
    int tid = threadIdx.x;
    __shared__ float qr[4];

    if (bid == 224) {
        float v = 0.f;
        if (tid < 128) v = 0.5f * s_w2[tid] * s_w1[3 * R * H + tid];
#pragma unroll
        for (int o = 16; o; o >>= 1) v += __shfl_xor_sync(0xFFFFFFFFu, v, o);
        if (tid < 128 && (tid & 31) == 0) qr[tid >> 5] = v;
        __syncthreads();
        if (tid == 0) d_Qw = qr[0] + qr[1] + qr[2] + qr[3];
        return;
    }
    if (bid >= 192) {
        int i0 = (bid - 192) * 1024 + tid;
#pragma unroll
        for (int t = 0; t < 4; t++) {
            int i = i0 + t * 256;
            float wd = s_w1[2 * R * H + i];
            d_Wxd[i] = s_w1[i] - wd;
            d_Wyd[i] = s_w1[R * H + i] + wd;
        }
        return;
    }

    int mi = bid / 64;
    int r0 = (bid % 64) * 8;
    const float* X = (mi == 0) ? fx : (mi == 1 ? fp : fn);

    __shared__ float xs[8][D];
    __shared__ float hs[8][HG];
    __shared__ float wsum[8][8];

    for (int i = tid; i < 8 * D; i += 256)
        xs[i / D][i % D] = X[(r0 + i / D) * D + (i % D)];
    __syncthreads();

    int j = tid;
    float acc[8];
#pragma unroll
    for (int r = 0; r < 8; r++) acc[r] = 0.f;
    for (int k = 0; k < D; k += 4) {
        float w0  = w1[(k + 0) * HG + j];
        float w1v = w1[(k + 1) * HG + j];
        float w2v = w1[(k + 2) * HG + j];
        float w3  = w1[(k + 3) * HG + j];
#pragma unroll
        for (int r = 0; r < 8; r++) {
            float4 xv = *(const float4*)&xs[r][k];
            acc[r] = fmaf(xv.x, w0, acc[r]);
            acc[r] = fmaf(xv.y, w1v, acc[r]);
            acc[r] = fmaf(xv.z, w2v, acc[r]);
            acc[r] = fmaf(xv.w, w3, acc[r]);
        }
    }
    float bb = b1[j];
#pragma unroll
    for (int r = 0; r < 8; r++) hs[r][j] = gelu_exact(acc[r] + bb);
    __syncthreads();

    float a2[8];
#pragma unroll
    for (int r = 0; r < 8; r++) a2[r] = 0.f;
    for (int k = 0; k < HG; k += 4) {
        float w0  = w2[(k + 0) * R + j];
        float w1v = w2[(k + 1) * R + j];
        float w2v = w2[(k + 2) * R + j];
        float w3  = w2[(k + 3) * R + j];
#pragma unroll
        for (int r = 0; r < 8; r++) {
            float4 hv = *(const float4*)&hs[r][k];
            a2[r] = fmaf(hv.x, w0, a2[r]);
            a2[r] = fmaf(hv.y, w1v, a2[r]);
            a2[r] = fmaf(hv.z, w2v, a2[r]);
            a2[r] = fmaf(hv.w, w3, a2[r]);
        }
    }
    float b2v = b2[j];
    int w = tid >> 5, lane = tid & 31;
#pragma unroll
    for (int r = 0; r < 8; r++) {
        float v = a2[r] + b2v;
        d_rep[mi][r0 + r][j] = v;
        float s = v * v;
#pragma unroll
        for (int o = 16; o; o >>= 1) s += __shfl_xor_sync(0xFFFFFFFFu, s, o);
        if (lane == 0) wsum[w][r] = s;
    }
    __syncthreads();
    if (tid < 8) {
        float s = 0.f;
#pragma unroll
        for (int ww = 0; ww < 8; ww++) s += wsum[ww][tid];
        d_norm2[mi][r0 + tid] = s;
    }
}

// ================= K2: Gram (split-K) + A/Bt (+Qb) =================
__global__ void __launch_bounds__(256) k2_gram_ab(
    const float* __restrict__ s_b1, const float* __restrict__ s_w2)
{
    __shared__ float smbuf[2 * 32 * 68];
    __shared__ float qred[4][8];
    int bid = blockIdx.x;
    int tid = threadIdx.x;

    if (bid < 256) {
        int set = bid >> 7;
        int kh = (bid >> 6) & 1;
        int tt = bid & 63;
        int bn = (tt >> 3) * 64;
        int bm = (tt & 7) * 64;
        float (*xs)[68]  = (float(*)[68])smbuf;
        float (*ysm)[68] = (float(*)[68])(smbuf + 32 * 68);
        int ty = tid >> 4, tx = tid & 15;

        float acc[4][4];
#pragma unroll
        for (int i = 0; i < 4; i++)
#pragma unroll
            for (int jj = 0; jj < 4; jj++) acc[i][jj] = 0.f;

        for (int kc = kh * 4; kc < kh * 4 + 4; kc++) {
            __syncthreads();
#pragma unroll
            for (int p = 0; p < 8; p++) {
                int i = tid + p * 256;
                int n = i >> 5, k = i & 31;
                xs[k][n]  = d_rep[0][bn + n][kc * 32 + k];
                ysm[k][n] = d_rep[set + 1][bm + n][kc * 32 + k];
            }
            __syncthreads();
#pragma unroll
            for (int k = 0; k < 32; k++) {
                float4 xv = *(const float4*)&xs[k][ty * 4];
                float4 yv = *(const float4*)&ysm[k][tx * 4];
                float xa[4] = {xv.x, xv.y, xv.z, xv.w};
                float ya[4] = {yv.x, yv.y, yv.z, yv.w};
#pragma unroll
                for (int i = 0; i < 4; i++)
#pragma unroll
                    for (int jj = 0; jj < 4; jj++) acc[i][jj] += xa[i] * ya[jj];
            }
        }
#pragma unroll
        for (int i = 0; i < 4; i++) {
            float4 o = make_float4(acc[i][0], acc[i][1], acc[i][2], acc[i][3]);
            *(float4*)&d_G[set][kh][(bn + ty * 4 + i) * M + bm + tx * 4] = o;
        }
    } else {
        int ab = bid - 256;
        int mi = ab / 64;
        int r0 = (ab % 64) * 8;
        float (*ys)[R] = (float(*)[R])smbuf;
        float (*ps)[H] = (float(*)[H])(smbuf + 8 * R);

        for (int i = tid; i < 8 * R; i += 256)
            ys[i / R][i % R] = d_rep[mi][r0 + i / R][i % R];
        __syncthreads();

        int h = tid & 127;
        int half = tid >> 7;
        const float* Wc = (mi == 0) ? d_Wxd : d_Wyd;
        float acc[8];
#pragma unroll
        for (int r = 0; r < 8; r++) acc[r] = 0.f;
        int kbeg = half * 128;
        for (int k = kbeg; k < kbeg + 128; k += 4) {
            float w0  = Wc[(k + 0) * H + h];
            float w1v = Wc[(k + 1) * H + h];
            float w2v = Wc[(k + 2) * H + h];
            float w3  = Wc[(k + 3) * H + h];
#pragma unroll
            for (int r = 0; r < 8; r++) {
                float4 yv = *(const float4*)&ys[r][k];
                acc[r] = fmaf(yv.x, w0, acc[r]);
                acc[r] = fmaf(yv.y, w1v, acc[r]);
                acc[r] = fmaf(yv.z, w2v, acc[r]);
                acc[r] = fmaf(yv.w, w3, acc[r]);
            }
        }
        if (half == 1) {
#pragma unroll
            for (int r = 0; r < 8; r++) ps[r][h] = acc[r];
        }
        __syncthreads();
        if (half == 0) {
            if (mi == 0) {
                float bb = s_b1[h];
#pragma unroll
                for (int r = 0; r < 8; r++)
                    d_A[(r0 + r) * H + h] = (acc[r] + ps[r][h] + bb) * INV_SQRT2;
            } else {
                float s2h = 0.70710678f * s_w2[h];
                int w = tid >> 5, lane = tid & 31;
#pragma unroll
                for (int r = 0; r < 8; r++) {
                    float btv = (acc[r] + ps[r][h]) * INV_SQRT2;
                    d_Bt[mi - 1][h * M + (r0 + r)] = btv;
                    float pr = s2h * btv;
#pragma unroll
                    for (int o = 16; o; o >>= 1) pr += __shfl_xor_sync(0xFFFFFFFFu, pr, o);
                    if (lane == 0) qred[w][r] = pr;
                }
            }
        }
        __syncthreads();
        if (mi > 0 && tid < 8)
            d_Qb[mi - 1][r0 + tid] = qred[0][tid] + qred[1][tid] + qred[2][tid] + qred[3][tid];
    }
}

// ================= K3: score + softmax (R10 version: 1 row/block, merged-u) =================
// grid = 2 sets x 512 rows = 1024 blocks, 256 threads; thread owns m = 2*tid, 2*tid+1
__global__ void __launch_bounds__(256) k3_score(
    const float* __restrict__ s_w1, const float* __restrict__ s_w2)
{
    int set = blockIdx.x >> 9;
    int n = blockIdx.x & 511;
    __shared__ float As[H];
    __shared__ float2 ws[H];   // (wnh, s2h)
    __shared__ float red[16];

    int tid = threadIdx.x;
    if (tid < H) {
        As[tid] = d_A[n * H + tid];
        float wn = s_w1[3 * R * H + tid] * INV_SQRT2;
        float s2 = s_w2[tid] * 0.70710678f;
        ws[tid] = make_float2(wn, s2);
    }
    __syncthreads();

    float nx = d_norm2[0][n];
    float2 ny = *(const float2*)&d_norm2[set + 1][2 * tid];
    float2 g0 = *(const float2*)&d_G[set][0][n * M + 2 * tid];
    float2 g1 = *(const float2*)&d_G[set][1][n * M + 2 * tid];
    float t0 = sqrtf(fmaxf(nx + ny.x - 2.f * (g0.x + g1.x), 0.f));
    float t1 = sqrtf(fmaxf(nx + ny.y - 2.f * (g0.y + g1.y), 0.f));
    float2 qb = *(const float2*)&d_Qb[set][2 * tid];
    float qw = d_Qw;

    float acc0 = 0.f, acc1 = 0.f;
    const float2* Bt2 = (const float2*)&d_Bt[set][0];

#pragma unroll 4
    for (int k = 0; k < H; k++) {
        float2 bv = Bt2[k * 256 + tid];
        float a = As[k];
        float2 wsp = ws[k];
        {
            float p = fmaf(t0, wsp.x, a + bv.x);
            float ap = fabsf(p);
            float dd = fmaf(0.47047f, ap, 1.f);
            float rc; asm("rcp.approx.f32 %0,%1;" : "=f"(rc) : "f"(dd));
            float hh = fmaf(-0.7478556f, rc, 0.0958798f);
            hh = fmaf(hh, rc, -0.3480242f);
            float pln = hh * rc;
            float ex = __expf(-p * p);
            float qs = wsp.y * ap;
            float u = fmaf(pln, ex, 1.0f);
            acc0 = fmaf(qs, u, acc0);
        }
        {
            float p = fmaf(t1, wsp.x, a + bv.y);
            float ap = fabsf(p);
            float dd = fmaf(0.47047f, ap, 1.f);
            float rc; asm("rcp.approx.f32 %0,%1;" : "=f"(rc) : "f"(dd));
            float hh = fmaf(-0.7478556f, rc, 0.0958798f);
            hh = fmaf(hh, rc, -0.3480242f);
            float pln = hh * rc;
            float ex = __expf(-p * p);
            float qs = wsp.y * ap;
            float u = fmaf(pln, ex, 1.0f);
            acc1 = fmaf(qs, u, acc1);
        }
    }

    float l0 = fmaf(t0, qw, qb.x) + acc0;
    float l1 = fmaf(t1, qw, qb.y) + acc1;

    int w = tid >> 5, lane = tid & 31;
    float mx = fmaxf(l0, l1);
#pragma unroll
    for (int o = 16; o; o >>= 1) mx = fmaxf(mx, __shfl_xor_sync(0xFFFFFFFFu, mx, o));
    if (lane == 0) red[w] = mx;
    __syncthreads();
    mx = red[0];
#pragma unroll
    for (int i = 1; i < 8; i++) mx = fmaxf(mx, red[i]);
    float e0 = __expf(l0 - mx), e1 = __expf(l1 - mx);
    float s = e0 + e1;
#pragma unroll
    for (int o = 16; o; o >>= 1) s += __shfl_xor_sync(0xFFFFFFFFu, s, o);
    if (lane == 0) red[8 + w] = s;
    __syncthreads();
    s = red[8];
#pragma unroll
    for (int i = 9; i < 16; i++) s += red[i];
    float inv = 1.f / s;
    *(float2*)&d_W[set][n * M + 2 * tid] = make_float2(e0 * inv, e1 * inv);
}

// ================= K4a: U partials, 64x64 tiles, 4x4 micro, 8-way M split =================
// grid = 32 tiles (8n x 4r) x 8 ms = 256 blocks, 256 threads
__global__ void __launch_bounds__(256) k4a_u()
{
    __shared__ float w_s[2][2][16][68];
    __shared__ float yp_s[2][16][64];
    __shared__ float yn_s[2][16][64];

    int bid = blockIdx.x;
    int ms = bid & 7;
    int tile = bid >> 3;
    int bn = (tile >> 2) * 64;
    int br = (tile & 3) * 64;
    int tid = threadIdx.x;
    int ty = tid >> 4;
    int tx = tid & 15;

    int wset = tid >> 7;
    int widx = tid & 127;
    int wn_l = widx >> 1;
    int wm_l = (widx & 1) * 8;
    int ykk = tid >> 4;
    int yc = (tid & 15) * 4;

    float acc[4][4];
#pragma unroll
    for (int i = 0; i < 4; i++)
#pragma unroll
        for (int j = 0; j < 4; j++) acc[i][j] = 0.f;

    int mbase = ms * 64;
    float4 wv0, wv1, ypv, ynv;
    {
        const float* wrow = &d_W[wset][(bn + wn_l) * M + mbase + wm_l];
        wv0 = *(const float4*)&wrow[0];
        wv1 = *(const float4*)&wrow[4];
        ypv = *(const float4*)&d_rep[1][mbase + ykk][br + yc];
        ynv = *(const float4*)&d_rep[2][mbase + ykk][br + yc];
    }
    {
        float wa[8] = {wv0.x, wv0.y, wv0.z, wv0.w, wv1.x, wv1.y, wv1.z, wv1.w};
#pragma unroll
        for (int q = 0; q < 8; q++) w_s[0][wset][wm_l + q][wn_l] = wa[q];
        *(float4*)&yp_s[0][ykk][yc] = ypv;
        *(float4*)&yn_s[0][ykk][yc] = ynv;
    }
    __syncthreads();

    int buf = 0;
    for (int mc = 0; mc < 4; mc++) {
        if (mc < 3) {
            int mrow = mbase + (mc + 1) * 16;
            const float* wrow = &d_W[wset][(bn + wn_l) * M + mrow + wm_l];
            wv0 = *(const float4*)&wrow[0];
            wv1 = *(const float4*)&wrow[4];
            ypv = *(const float4*)&d_rep[1][mrow + ykk][br + yc];
            ynv = *(const float4*)&d_rep[2][mrow + ykk][br + yc];
        }
#pragma unroll
        for (int kk = 0; kk < 16; kk++) {
            float4 wp = *(const float4*)&w_s[buf][0][kk][ty * 4];
            float4 wq = *(const float4*)&w_s[buf][1][kk][ty * 4];
            float4 yp = *(const float4*)&yp_s[buf][kk][tx * 4];
            float4 yn = *(const float4*)&yn_s[buf][kk][tx * 4];
            float wpa[4] = {wp.x, wp.y, wp.z, wp.w};
            float wqa[4] = {wq.x, wq.y, wq.z, wq.w};
            float ypa[4] = {yp.x, yp.y, yp.z, yp.w};
            float yna[4] = {yn.x, yn.y, yn.z, yn.w};
#pragma unroll
            for (int i = 0; i < 4; i++)
#pragma unroll
                for (int j = 0; j < 4; j++) {
                    acc[i][j] = fmaf(wpa[i], ypa[j], acc[i][j]);
                    acc[i][j] = fmaf(-wqa[i], yna[j], acc[i][j]);
                }
        }
        if (mc < 3) {
            __syncthreads();
            int nb = buf ^ 1;
            float wa[8] = {wv0.x, wv0.y, wv0.z, wv0.w, wv1.x, wv1.y, wv1.z, wv1.w};
#pragma unroll
            for (int q = 0; q < 8; q++) w_s[nb][wset][wm_l + q][wn_l] = wa[q];
            *(float4*)&yp_s[nb][ykk][yc] = ypv;
            *(float4*)&yn_s[nb][ykk][yc] = ynv;
            __syncthreads();
            buf = nb;
        }
    }
#pragma unroll
    for (int i = 0; i < 4; i++) {
        float4 o = make_float4(acc[i][0], acc[i][1], acc[i][2], acc[i][3]);
        *(float4*)&d_Upart[ms][bn + ty * 4 + i][br + tx * 4] = o;
    }
}

// ================= K4b: out = (sum of 8 U partials) @ out_w =================
__global__ void __launch_bounds__(256) k4b_out(const float* __restrict__ out_w,
                                               float* __restrict__ out)
{
    __shared__ float us[16][36];
    __shared__ float ws[16][64];

    int bid = blockIdx.x;
    int bn = (bid >> 3) * 32;
    int bd = (bid & 7) * 64;
    int tid = threadIdx.x;
    int ty = tid >> 4, tx = tid & 15;

    float acc[2][4];
#pragma unroll
    for (int i = 0; i < 2; i++)
#pragma unroll
        for (int j = 0; j < 4; j++) acc[i][j] = 0.f;

    int un = tid >> 2;
    int uk = (tid & 3) * 4;
    int t2 = tid - 128;
    int wkk = t2 >> 3;
    int wc = (t2 & 7) * 8;

    for (int kc = 0; kc < R / 16; kc++) {
        float4 uv; float4 wv0, wv1;
        if (tid < 128) {
            float4 p[8];
#pragma unroll
            for (int q = 0; q < 8; q++)
                p[q] = *(const float4*)&d_Upart[q][bn + un][kc * 16 + uk];
            uv = p[0];
#pragma unroll
            for (int q = 1; q < 8; q++) {
                uv.x += p[q].x; uv.y += p[q].y; uv.z += p[q].z; uv.w += p[q].w;
            }
        } else {
            wv0 = *(const float4*)&out_w[(kc * 16 + wkk) * D + bd + wc];
            wv1 = *(const float4*)&out_w[(kc * 16 + wkk) * D + bd + wc + 4];
        }
        __syncthreads();
        if (tid < 128) {
            us[uk + 0][un] = uv.x;
            us[uk + 1][un] = uv.y;
            us[uk + 2][un] = uv.z;
            us[uk + 3][un] = uv.w;
        } else {
            *(float4*)&ws[wkk][wc] = wv0;
            *(float4*)&ws[wkk][wc + 4] = wv1;
        }
        __syncthreads();
#pragma unroll
        for (int kk = 0; kk < 16; kk++) {
            float2 u01 = *(const float2*)&us[kk][ty * 2];
            float4 w4 = *(const float4*)&ws[kk][tx * 4];
            float wa[4] = {w4.x, w4.y, w4.z, w4.w};
#pragma unroll
            for (int j = 0; j < 4; j++) {
                acc[0][j] += u01.x * wa[j];
                acc[1][j] += u01.y * wa[j];
            }
        }
    }
#pragma unroll
    for (int i = 0; i < 2; i++) {
        float4 o = make_float4(acc[i][0], acc[i][1], acc[i][2], acc[i][3]);
        *(float4*)&out[(bn + ty * 2 + i) * D + bd + tx * 4] = o;
    }
}

// ---------------- launch ----------------
extern "C" void kernel_launch(void* const* d_in, const int* in_sizes, int n_in,
                              void* d_out, int out_size)
{
    const float* feat_x  = (const float*)d_in[0];
    const float* feat_pos= (const float*)d_in[1];
    const float* feat_neg= (const float*)d_in[2];
    const float* g_w1    = (const float*)d_in[3];
    const float* g_b1    = (const float*)d_in[4];
    const float* g_w2    = (const float*)d_in[5];
    const float* g_b2    = (const float*)d_in[6];
    const float* out_w   = (const float*)d_in[7];
    const float* s_w1    = (const float*)d_in[8];
    const float* s_b1    = (const float*)d_in[9];
    const float* s_w2    = (const float*)d_in[10];
    float* out = (float*)d_out;
    (void)in_sizes; (void)n_in; (void)out_size;

    k1_gmlp<<<225, 256>>>(feat_x, feat_pos, feat_neg, g_w1, g_b1, g_w2, g_b2, s_w1, s_w2);
    k2_gram_ab<<<448, 256>>>(s_b1, s_w2);
    k3_score<<<1024, 256>>>(s_w1, s_w2);
    k4a_u<<<256, 256>>>();
    k4b_out<<<128, 256>>>(out_w, out);
}

// round 13
// speedup vs baseline: 1.2189x; 1.1219x over previous
#include <cuda_runtime.h>
#include <math.h>

#define N 512
#define M 512
#define D 512
#define HG 256
#define R 256
#define H 128

// ---------------- device scratch ----------------
__device__ float d_rep[3][N][R];
__device__ float d_norm2[3][N];
__device__ float d_Wxd[R * H];
__device__ float d_Wyd[R * H];
__device__ float d_A[N * H];        // pre-scaled by 1/sqrt(2)
__device__ float d_Bt[2][H * M];    // pre-scaled by 1/sqrt(2)
__device__ float d_G[2][2][N * M];  // gram split-K partials
__device__ float d_W[2][N * M];
__device__ float d_Upart[8][N][R];
__device__ float d_Qb[2][M];
__device__ float d_Qw;

#define INV_SQRT2 0.7071067811865476f

__device__ __forceinline__ float gelu_exact(float x) {
    return 0.5f * x * (1.0f + erff(x * INV_SQRT2));
}

// ================= K1: fused g-MLP, Wxd/Wyd combine, Qw =================
__global__ void __launch_bounds__(256) k1_gmlp(
    const float* __restrict__ fx, const float* __restrict__ fp, const float* __restrict__ fn,
    const float* __restrict__ w1, const float* __restrict__ b1,
    const float* __restrict__ w2, const float* __restrict__ b2,
    const float* __restrict__ s_w1, const float* __restrict__ s_w2)
{
    int bid = blockIdx.x;
    int tid = threadIdx.x;
    __shared__ float qr[4];

    if (bid == 224) {
        float v = 0.f;
        if (tid < 128) v = 0.5f * s_w2[tid] * s_w1[3 * R * H + tid];
#pragma unroll
        for (int o = 16; o; o >>= 1) v += __shfl_xor_sync(0xFFFFFFFFu, v, o);
        if (tid < 128 && (tid & 31) == 0) qr[tid >> 5] = v;
        __syncthreads();
        if (tid == 0) d_Qw = qr[0] + qr[1] + qr[2] + qr[3];
        return;
    }
    if (bid >= 192) {
        int i0 = (bid - 192) * 1024 + tid;
#pragma unroll
        for (int t = 0; t < 4; t++) {
            int i = i0 + t * 256;
            float wd = s_w1[2 * R * H + i];
            d_Wxd[i] = s_w1[i] - wd;
            d_Wyd[i] = s_w1[R * H + i] + wd;
        }
        return;
    }

    int mi = bid / 64;
    int r0 = (bid % 64) * 8;
    const float* X = (mi == 0) ? fx : (mi == 1 ? fp : fn);

    __shared__ float xs[8][D];
    __shared__ float hs[8][HG];
    __shared__ float wsum[8][8];

    for (int i = tid; i < 8 * D; i += 256)
        xs[i / D][i % D] = X[(r0 + i / D) * D + (i % D)];
    __syncthreads();

    int j = tid;
    float acc[8];
#pragma unroll
    for (int r = 0; r < 8; r++) acc[r] = 0.f;
    for (int k = 0; k < D; k += 4) {
        float w0  = w1[(k + 0) * HG + j];
        float w1v = w1[(k + 1) * HG + j];
        float w2v = w1[(k + 2) * HG + j];
        float w3  = w1[(k + 3) * HG + j];
#pragma unroll
        for (int r = 0; r < 8; r++) {
            float4 xv = *(const float4*)&xs[r][k];
            acc[r] = fmaf(xv.x, w0, acc[r]);
            acc[r] = fmaf(xv.y, w1v, acc[r]);
            acc[r] = fmaf(xv.z, w2v, acc[r]);
            acc[r] = fmaf(xv.w, w3, acc[r]);
        }
    }
    float bb = b1[j];
#pragma unroll
    for (int r = 0; r < 8; r++) hs[r][j] = gelu_exact(acc[r] + bb);
    __syncthreads();

    float a2[8];
#pragma unroll
    for (int r = 0; r < 8; r++) a2[r] = 0.f;
    for (int k = 0; k < HG; k += 4) {
        float w0  = w2[(k + 0) * R + j];
        float w1v = w2[(k + 1) * R + j];
        float w2v = w2[(k + 2) * R + j];
        float w3  = w2[(k + 3) * R + j];
#pragma unroll
        for (int r = 0; r < 8; r++) {
            float4 hv = *(const float4*)&hs[r][k];
            a2[r] = fmaf(hv.x, w0, a2[r]);
            a2[r] = fmaf(hv.y, w1v, a2[r]);
            a2[r] = fmaf(hv.z, w2v, a2[r]);
            a2[r] = fmaf(hv.w, w3, a2[r]);
        }
    }
    float b2v = b2[j];
    int w = tid >> 5, lane = tid & 31;
#pragma unroll
    for (int r = 0; r < 8; r++) {
        float v = a2[r] + b2v;
        d_rep[mi][r0 + r][j] = v;
        float s = v * v;
#pragma unroll
        for (int o = 16; o; o >>= 1) s += __shfl_xor_sync(0xFFFFFFFFu, s, o);
        if (lane == 0) wsum[w][r] = s;
    }
    __syncthreads();
    if (tid < 8) {
        float s = 0.f;
#pragma unroll
        for (int ww = 0; ww < 8; ww++) s += wsum[ww][tid];
        d_norm2[mi][r0 + tid] = s;
    }
}

// ================= K2: Gram (split-K) + A/Bt (+Qb) =================
__global__ void __launch_bounds__(256) k2_gram_ab(
    const float* __restrict__ s_b1, const float* __restrict__ s_w2)
{
    __shared__ float smbuf[2 * 32 * 68];
    __shared__ float qred[4][8];
    int bid = blockIdx.x;
    int tid = threadIdx.x;

    if (bid < 256) {
        int set = bid >> 7;
        int kh = (bid >> 6) & 1;
        int tt = bid & 63;
        int bn = (tt >> 3) * 64;
        int bm = (tt & 7) * 64;
        float (*xs)[68]  = (float(*)[68])smbuf;
        float (*ysm)[68] = (float(*)[68])(smbuf + 32 * 68);
        int ty = tid >> 4, tx = tid & 15;

        float acc[4][4];
#pragma unroll
        for (int i = 0; i < 4; i++)
#pragma unroll
            for (int jj = 0; jj < 4; jj++) acc[i][jj] = 0.f;

        for (int kc = kh * 4; kc < kh * 4 + 4; kc++) {
            __syncthreads();
#pragma unroll
            for (int p = 0; p < 8; p++) {
                int i = tid + p * 256;
                int n = i >> 5, k = i & 31;
                xs[k][n]  = d_rep[0][bn + n][kc * 32 + k];
                ysm[k][n] = d_rep[set + 1][bm + n][kc * 32 + k];
            }
            __syncthreads();
#pragma unroll
            for (int k = 0; k < 32; k++) {
                float4 xv = *(const float4*)&xs[k][ty * 4];
                float4 yv = *(const float4*)&ysm[k][tx * 4];
                float xa[4] = {xv.x, xv.y, xv.z, xv.w};
                float ya[4] = {yv.x, yv.y, yv.z, yv.w};
#pragma unroll
                for (int i = 0; i < 4; i++)
#pragma unroll
                    for (int jj = 0; jj < 4; jj++) acc[i][jj] += xa[i] * ya[jj];
            }
        }
#pragma unroll
        for (int i = 0; i < 4; i++) {
            float4 o = make_float4(acc[i][0], acc[i][1], acc[i][2], acc[i][3]);
            *(float4*)&d_G[set][kh][(bn + ty * 4 + i) * M + bm + tx * 4] = o;
        }
    } else {
        int ab = bid - 256;
        int mi = ab / 64;
        int r0 = (ab % 64) * 8;
        float (*ys)[R] = (float(*)[R])smbuf;
        float (*ps)[H] = (float(*)[H])(smbuf + 8 * R);

        for (int i = tid; i < 8 * R; i += 256)
            ys[i / R][i % R] = d_rep[mi][r0 + i / R][i % R];
        __syncthreads();

        int h = tid & 127;
        int half = tid >> 7;
        const float* Wc = (mi == 0) ? d_Wxd : d_Wyd;
        float acc[8];
#pragma unroll
        for (int r = 0; r < 8; r++) acc[r] = 0.f;
        int kbeg = half * 128;
        for (int k = kbeg; k < kbeg + 128; k += 4) {
            float w0  = Wc[(k + 0) * H + h];
            float w1v = Wc[(k + 1) * H + h];
            float w2v = Wc[(k + 2) * H + h];
            float w3  = Wc[(k + 3) * H + h];
#pragma unroll
            for (int r = 0; r < 8; r++) {
                float4 yv = *(const float4*)&ys[r][k];
                acc[r] = fmaf(yv.x, w0, acc[r]);
                acc[r] = fmaf(yv.y, w1v, acc[r]);
                acc[r] = fmaf(yv.z, w2v, acc[r]);
                acc[r] = fmaf(yv.w, w3, acc[r]);
            }
        }
        if (half == 1) {
#pragma unroll
            for (int r = 0; r < 8; r++) ps[r][h] = acc[r];
        }
        __syncthreads();
        if (half == 0) {
            if (mi == 0) {
                float bb = s_b1[h];
#pragma unroll
                for (int r = 0; r < 8; r++)
                    d_A[(r0 + r) * H + h] = (acc[r] + ps[r][h] + bb) * INV_SQRT2;
            } else {
                float s2h = 0.70710678f * s_w2[h];
                int w = tid >> 5, lane = tid & 31;
#pragma unroll
                for (int r = 0; r < 8; r++) {
                    float btv = (acc[r] + ps[r][h]) * INV_SQRT2;
                    d_Bt[mi - 1][h * M + (r0 + r)] = btv;
                    float pr = s2h * btv;
#pragma unroll
                    for (int o = 16; o; o >>= 1) pr += __shfl_xor_sync(0xFFFFFFFFu, pr, o);
                    if (lane == 0) qred[w][r] = pr;
                }
            }
        }
        __syncthreads();
        if (mi > 0 && tid < 8)
            d_Qb[mi - 1][r0 + tid] = qred[0][tid] + qred[1][tid] + qred[2][tid] + qred[3][tid];
    }
}

// ================= K3: score + softmax (single-MUFU erfc via exp2 fit) =================
// erfc(x) ~= 2^(x * g(x)), g quartic; abs erf err <= ~2.5e-4 on [0,inf)
// grid = 2 sets x 512 rows = 1024 blocks, 256 threads; thread owns m = 2*tid, 2*tid+1
__global__ void __launch_bounds__(256) k3_score(
    const float* __restrict__ s_w1, const float* __restrict__ s_w2)
{
    int set = blockIdx.x >> 9;
    int n = blockIdx.x & 511;
    __shared__ float As[H];
    __shared__ float2 ws[H];   // (wnh, s2h)
    __shared__ float red[16];

    int tid = threadIdx.x;
    if (tid < H) {
        As[tid] = d_A[n * H + tid];
        float wn = s_w1[3 * R * H + tid] * INV_SQRT2;
        float s2 = s_w2[tid] * 0.70710678f;
        ws[tid] = make_float2(wn, s2);
    }
    __syncthreads();

    float nx = d_norm2[0][n];
    float2 ny = *(const float2*)&d_norm2[set + 1][2 * tid];
    float2 g0 = *(const float2*)&d_G[set][0][n * M + 2 * tid];
    float2 g1 = *(const float2*)&d_G[set][1][n * M + 2 * tid];
    float t0 = sqrtf(fmaxf(nx + ny.x - 2.f * (g0.x + g1.x), 0.f));
    float t1 = sqrtf(fmaxf(nx + ny.y - 2.f * (g0.y + g1.y), 0.f));
    float2 qb = *(const float2*)&d_Qb[set][2 * tid];
    float qw = d_Qw;

    float acc0 = 0.f, acc1 = 0.f;
    const float2* Bt2 = (const float2*)&d_Bt[set][0];

    // g(x) coefficients pre-scaled by -log2(e):
    // f(x) = -ln erfc(x) = x*(1.1284 + 0.64127x + 0.09464x^2 - 0.015645x^3 + 0.001135x^4)
    const float A0 = -1.6280352f;
    const float B1 = -0.9251750f;
    const float C2 = -0.1365413f;
    const float D3 =  0.0225709f;
    const float E4 = -0.0016375f;

#pragma unroll 4
    for (int k = 0; k < H; k++) {
        float2 bv = Bt2[k * 256 + tid];
        float a = As[k];
        float2 wsp = ws[k];
        {
            float p = fmaf(t0, wsp.x, a + bv.x);
            float x = fabsf(p);
            float h = fmaf(E4, x, D3);
            h = fmaf(h, x, C2);
            h = fmaf(h, x, B1);
            h = fmaf(h, x, A0);
            float e2;
            asm("ex2.approx.f32 %0,%1;" : "=f"(e2) : "f"(h * x));  // erfc(x)
            float sx = wsp.y * x;
            float u = fmaf(e2, -1.f, 1.f);                          // erf(x)
            acc0 = fmaf(sx, u, acc0);
        }
        {
            float p = fmaf(t1, wsp.x, a + bv.y);
            float x = fabsf(p);
            float h = fmaf(E4, x, D3);
            h = fmaf(h, x, C2);
            h = fmaf(h, x, B1);
            h = fmaf(h, x, A0);
            float e2;
            asm("ex2.approx.f32 %0,%1;" : "=f"(e2) : "f"(h * x));
            float sx = wsp.y * x;
            float u = fmaf(e2, -1.f, 1.f);
            acc1 = fmaf(sx, u, acc1);
        }
    }

    float l0 = fmaf(t0, qw, qb.x) + acc0;
    float l1 = fmaf(t1, qw, qb.y) + acc1;

    int w = tid >> 5, lane = tid & 31;
    float mx = fmaxf(l0, l1);
#pragma unroll
    for (int o = 16; o; o >>= 1) mx = fmaxf(mx, __shfl_xor_sync(0xFFFFFFFFu, mx, o));
    if (lane == 0) red[w] = mx;
    __syncthreads();
    mx = red[0];
#pragma unroll
    for (int i = 1; i < 8; i++) mx = fmaxf(mx, red[i]);
    float e0 = __expf(l0 - mx), e1 = __expf(l1 - mx);
    float s = e0 + e1;
#pragma unroll
    for (int o = 16; o; o >>= 1) s += __shfl_xor_sync(0xFFFFFFFFu, s, o);
    if (lane == 0) red[8 + w] = s;
    __syncthreads();
    s = red[8];
#pragma unroll
    for (int i = 9; i < 16; i++) s += red[i];
    float inv = 1.f / s;
    *(float2*)&d_W[set][n * M + 2 * tid] = make_float2(e0 * inv, e1 * inv);
}

// ================= K4a: U partials, 64x64 tiles, 4x4 micro, 8-way M split =================
__global__ void __launch_bounds__(256) k4a_u()
{
    __shared__ float w_s[2][2][16][68];
    __shared__ float yp_s[2][16][64];
    __shared__ float yn_s[2][16][64];

    int bid = blockIdx.x;
    int ms = bid & 7;
    int tile = bid >> 3;
    int bn = (tile >> 2) * 64;
    int br = (tile & 3) * 64;
    int tid = threadIdx.x;
    int ty = tid >> 4;
    int tx = tid & 15;

    int wset = tid >> 7;
    int widx = tid & 127;
    int wn_l = widx >> 1;
    int wm_l = (widx & 1) * 8;
    int ykk = tid >> 4;
    int yc = (tid & 15) * 4;

    float acc[4][4];
#pragma unroll
    for (int i = 0; i < 4; i++)
#pragma unroll
        for (int j = 0; j < 4; j++) acc[i][j] = 0.f;

    int mbase = ms * 64;
    float4 wv0, wv1, ypv, ynv;
    {
        const float* wrow = &d_W[wset][(bn + wn_l) * M + mbase + wm_l];
        wv0 = *(const float4*)&wrow[0];
        wv1 = *(const float4*)&wrow[4];
        ypv = *(const float4*)&d_rep[1][mbase + ykk][br + yc];
        ynv = *(const float4*)&d_rep[2][mbase + ykk][br + yc];
    }
    {
        float wa[8] = {wv0.x, wv0.y, wv0.z, wv0.w, wv1.x, wv1.y, wv1.z, wv1.w};
#pragma unroll
        for (int q = 0; q < 8; q++) w_s[0][wset][wm_l + q][wn_l] = wa[q];
        *(float4*)&yp_s[0][ykk][yc] = ypv;
        *(float4*)&yn_s[0][ykk][yc] = ynv;
    }
    __syncthreads();

    int buf = 0;
    for (int mc = 0; mc < 4; mc++) {
        if (mc < 3) {
            int mrow = mbase + (mc + 1) * 16;
            const float* wrow = &d_W[wset][(bn + wn_l) * M + mrow + wm_l];
            wv0 = *(const float4*)&wrow[0];
            wv1 = *(const float4*)&wrow[4];
            ypv = *(const float4*)&d_rep[1][mrow + ykk][br + yc];
            ynv = *(const float4*)&d_rep[2][mrow + ykk][br + yc];
        }
#pragma unroll
        for (int kk = 0; kk < 16; kk++) {
            float4 wp = *(const float4*)&w_s[buf][0][kk][ty * 4];
            float4 wq = *(const float4*)&w_s[buf][1][kk][ty * 4];
            float4 yp = *(const float4*)&yp_s[buf][kk][tx * 4];
            float4 yn = *(const float4*)&yn_s[buf][kk][tx * 4];
            float wpa[4] = {wp.x, wp.y, wp.z, wp.w};
            float wqa[4] = {wq.x, wq.y, wq.z, wq.w};
            float ypa[4] = {yp.x, yp.y, yp.z, yp.w};
            float yna[4] = {yn.x, yn.y, yn.z, yn.w};
#pragma unroll
            for (int i = 0; i < 4; i++)
#pragma unroll
                for (int j = 0; j < 4; j++) {
                    acc[i][j] = fmaf(wpa[i], ypa[j], acc[i][j]);
                    acc[i][j] = fmaf(-wqa[i], yna[j], acc[i][j]);
                }
        }
        if (mc < 3) {
            __syncthreads();
            int nb = buf ^ 1;
            float wa[8] = {wv0.x, wv0.y, wv0.z, wv0.w, wv1.x, wv1.y, wv1.z, wv1.w};
#pragma unroll
            for (int q = 0; q < 8; q++) w_s[nb][wset][wm_l + q][wn_l] = wa[q];
            *(float4*)&yp_s[nb][ykk][yc] = ypv;
            *(float4*)&yn_s[nb][ykk][yc] = ynv;
            __syncthreads();
            buf = nb;
        }
    }
#pragma unroll
    for (int i = 0; i < 4; i++) {
        float4 o = make_float4(acc[i][0], acc[i][1], acc[i][2], acc[i][3]);
        *(float4*)&d_Upart[ms][bn + ty * 4 + i][br + tx * 4] = o;
    }
}

// ================= K4b: out = (sum of 8 U partials) @ out_w =================
__global__ void __launch_bounds__(256) k4b_out(const float* __restrict__ out_w,
                                               float* __restrict__ out)
{
    __shared__ float us[16][36];
    __shared__ float ws[16][64];

    int bid = blockIdx.x;
    int bn = (bid >> 3) * 32;
    int bd = (bid & 7) * 64;
    int tid = threadIdx.x;
    int ty = tid >> 4, tx = tid & 15;

    float acc[2][4];
#pragma unroll
    for (int i = 0; i < 2; i++)
#pragma unroll
        for (int j = 0; j < 4; j++) acc[i][j] = 0.f;

    int un = tid >> 2;
    int uk = (tid & 3) * 4;
    int t2 = tid - 128;
    int wkk = t2 >> 3;
    int wc = (t2 & 7) * 8;

    for (int kc = 0; kc < R / 16; kc++) {
        float4 uv; float4 wv0, wv1;
        if (tid < 128) {
            float4 p[8];
#pragma unroll
            for (int q = 0; q < 8; q++)
                p[q] = *(const float4*)&d_Upart[q][bn + un][kc * 16 + uk];
            uv = p[0];
#pragma unroll
            for (int q = 1; q < 8; q++) {
                uv.x += p[q].x; uv.y += p[q].y; uv.z += p[q].z; uv.w += p[q].w;
            }
        } else {
            wv0 = *(const float4*)&out_w[(kc * 16 + wkk) * D + bd + wc];
            wv1 = *(const float4*)&out_w[(kc * 16 + wkk) * D + bd + wc + 4];
        }
        __syncthreads();
        if (tid < 128) {
            us[uk + 0][un] = uv.x;
            us[uk + 1][un] = uv.y;
            us[uk + 2][un] = uv.z;
            us[uk + 3][un] = uv.w;
        } else {
            *(float4*)&ws[wkk][wc] = wv0;
            *(float4*)&ws[wkk][wc + 4] = wv1;
        }
        __syncthreads();
#pragma unroll
        for (int kk = 0; kk < 16; kk++) {
            float2 u01 = *(const float2*)&us[kk][ty * 2];
            float4 w4 = *(const float4*)&ws[kk][tx * 4];
            float wa[4] = {w4.x, w4.y, w4.z, w4.w};
#pragma unroll
            for (int j = 0; j < 4; j++) {
                acc[0][j] += u01.x * wa[j];
                acc[1][j] += u01.y * wa[j];
            }
        }
    }
#pragma unroll
    for (int i = 0; i < 2; i++) {
        float4 o = make_float4(acc[i][0], acc[i][1], acc[i][2], acc[i][3]);
        *(float4*)&out[(bn + ty * 2 + i) * D + bd + tx * 4] = o;
    }
}

// ---------------- launch ----------------
extern "C" void kernel_launch(void* const* d_in, const int* in_sizes, int n_in,
                              void* d_out, int out_size)
{
    const float* feat_x  = (const float*)d_in[0];
    const float* feat_pos= (const float*)d_in[1];
    const float* feat_neg= (const float*)d_in[2];
    const float* g_w1    = (const float*)d_in[3];
    const float* g_b1    = (const float*)d_in[4];
    const float* g_w2    = (const float*)d_in[5];
    const float* g_b2    = (const float*)d_in[6];
    const float* out_w   = (const float*)d_in[7];
    const float* s_w1    = (const float*)d_in[8];
    const float* s_b1    = (const float*)d_in[9];
    const float* s_w2    = (const float*)d_in[10];
    float* out = (float*)d_out;
    (void)in_sizes; (void)n_in; (void)out_size;

    k1_gmlp<<<225, 256>>>(feat_x, feat_pos, feat_neg, g_w1, g_b1, g_w2, g_b2, s_w1, s_w2);
    k2_gram_ab<<<448, 256>>>(s_b1, s_w2);
    k3_score<<<1024, 256>>>(s_w1, s_w2);
    k4a_u<<<256, 256>>>();
    k4b_out<<<128, 256>>>(out_w, out);
}